// round 16
// baseline (speedup 1.0000x reference)
#include <cuda_runtime.h>

#define NSTEPS   50
#define T_DENSE  8
#define T_CACHED (NSTEPS - T_DENSE)
#define LRATE    0.1f
#define BMAX     8192

__device__ float g_c0[BMAX];
typedef unsigned long long u64;
typedef unsigned int u32;

__device__ __forceinline__ u64 pk2(float lo, float hi) {
    u64 r; asm("mov.b64 %0, {%1,%2};" : "=l"(r) : "f"(lo), "f"(hi)); return r;
}
__device__ __forceinline__ void upk2(u64 v, float& lo, float& hi) {
    asm("mov.b64 {%0,%1}, %2;" : "=f"(lo), "=f"(hi) : "l"(v));
}
__device__ __forceinline__ void fma2(u64& d, u64 a, u64 b) {
    asm("fma.rn.f32x2 %0, %1, %2, %0;" : "+l"(d) : "l"(a), "l"(b));
}
__device__ __forceinline__ u64 add2(u64 a, u64 b) {
    u64 r; asm("add.rn.f32x2 %0, %1, %2;" : "=l"(r) : "l"(a), "l"(b)); return r;
}

// ---------------- Kernel 1: 1-D nearest neighbor ----------------
// |ci-cj| == sqrt((ci-cj)^2) exactly in RN fp32. Dual-chain float2 ILP;
// first-index tiebreak preserved (strict < within ascending chains, explicit
// index compare on merge).
#define NN_TILE 2048
__global__ __launch_bounds__(256) void nn_kernel(const float* __restrict__ c, int B) {
    __shared__ float ct[NN_TILE];
    int lane = threadIdx.x & 31, w = threadIdx.x >> 5, q = blockIdx.x * 8 + w;
    float cq = (q < B) ? c[q] : 0.f;
    float dA = 3.0e38f, dB = 3.0e38f; int jA = 0, jB = 0;
    for (int t0 = 0; t0 < B; t0 += NN_TILE) {
        int nt = min(NN_TILE, B - t0);
        __syncthreads();
        for (int i = threadIdx.x; i < nt; i += 256) ct[i] = c[t0 + i];
        __syncthreads();
        for (int jj = lane * 2; jj < nt; jj += 64) {
            float2 v = *(const float2*)(ct + jj);
            int j0 = t0 + jj, j1 = j0 + 1;
            float d0 = fabsf(cq - v.x); if (j0 == q) d0 += 1e9f;
            float d1 = fabsf(cq - v.y); if (j1 == q) d1 += 1e9f;
            if (d0 < dA) { dA = d0; jA = j0; }
            if (d1 < dB) { dB = d1; jB = j1; }
        }
    }
    if (dB < dA || (dB == dA && jB < jA)) { dA = dB; jA = jB; }
#pragma unroll
    for (int off = 16; off; off >>= 1) {
        float dO = __shfl_down_sync(0xffffffffu, dA, off);
        int   jO = __shfl_down_sync(0xffffffffu, jA, off);
        if (dO < dA || (dO == dA && jO < jA)) { dA = dO; jA = jO; }
    }
    if (lane == 0 && q < B) g_c0[q] = c[jA];
}

// ---------------- Phase 1: dense (R4 winner) ----------------
__device__ __forceinline__ void mv_d(const float* __restrict__ W,
                                     const u64* __restrict__ A,
                                     int n0, int sG2, u64 acc[16]) {
#pragma unroll 8
    for (int k = 0; k < 64; k++) {
        ulonglong2 wA  = *(const ulonglong2*)(W + k * 64 + n0);
        ulonglong2 wB  = *(const ulonglong2*)(W + k * 64 + n0 + 4);
        ulonglong2 h01 = *(const ulonglong2*)(A + k * 64 + sG2);
        ulonglong2 h23 = *(const ulonglong2*)(A + k * 64 + 32 + sG2);
        fma2(acc[0],  wA.x, h01.x); fma2(acc[1],  wA.x, h01.y);
        fma2(acc[2],  wA.x, h23.x); fma2(acc[3],  wA.x, h23.y);
        fma2(acc[4],  wA.y, h01.x); fma2(acc[5],  wA.y, h01.y);
        fma2(acc[6],  wA.y, h23.x); fma2(acc[7],  wA.y, h23.y);
        fma2(acc[8],  wB.x, h01.x); fma2(acc[9],  wB.x, h01.y);
        fma2(acc[10], wB.x, h23.x); fma2(acc[11], wB.x, h23.y);
        fma2(acc[12], wB.y, h01.x); fma2(acc[13], wB.y, h01.y);
        fma2(acc[14], wB.y, h23.x); fma2(acc[15], wB.y, h23.y);
    }
}
__device__ __forceinline__ void unpack_d(const u64 acc[16], float v[8][4]) {
#pragma unroll
    for (int p = 0; p < 4; p++)
#pragma unroll
        for (int si = 0; si < 4; si++)
            upk2(acc[p * 4 + si], v[2 * p][si], v[2 * p + 1][si]);
}
__device__ __forceinline__ void store_dup_d(u64* __restrict__ Y, int n0, int sG2,
                                            const float v[8][4]) {
#pragma unroll
    for (int r = 0; r < 8; r++) {
        ulonglong2 t0, t1;
        t0.x = pk2(v[r][0], v[r][0]); t0.y = pk2(v[r][1], v[r][1]);
        t1.x = pk2(v[r][2], v[r][2]); t1.y = pk2(v[r][3], v[r][3]);
        *(ulonglong2*)(Y + (n0 + r) * 64 + sG2)      = t0;
        *(ulonglong2*)(Y + (n0 + r) * 64 + 32 + sG2) = t1;
    }
}

__global__ __launch_bounds__(128, 1) void solver_dense(
    const float* __restrict__ x,
    const float* __restrict__ W1, const float* __restrict__ b1,
    const float* __restrict__ W2, const float* __restrict__ b2,
    const float* __restrict__ W3, const float* __restrict__ b3,
    const float* __restrict__ W4, float* __restrict__ out, int nsteps)
{
    extern __shared__ __align__(16) char smraw[];
    float* W2T = (float*)smraw;
    float* W3T = W2T + 4096;
    float* W2N = W3T + 4096;
    float* W3N = W2N + 4096;
    u64*  ActA = (u64*)(W3N + 4096);
    u64*  ActB = ActA + 4096;
    u64*  b2d  = ActB + 4096;
    u64*  b3d  = b2d + 32;
    float* red = (float*)(b3d + 32);

    int tid = threadIdx.x, lane = tid & 31, warp = tid >> 5;
    int sG = tid & 15, nG = tid >> 4, n0 = nG * 8, sG2 = sG * 2;

    for (int i = tid; i < 1024; i += 128) {
        ((float4*)W2N)[i] = ((const float4*)W2)[i];
        ((float4*)W3N)[i] = ((const float4*)W3)[i];
    }
    __syncthreads();
    for (int i = tid; i < 4096; i += 128) {
        int n = i >> 6, k = i & 63;
        W2T[k * 64 + n] = W2N[i];
        W3T[k * 64 + n] = W3N[i];
    }
    if (tid < 32) {
        b2d[tid] = pk2(b2[2 * tid], b2[2 * tid + 1]);
        b3d[tid] = pk2(b3[2 * tid], b3[2 * tid + 1]);
    }

    int gs = blockIdx.x * 64 + sG * 4;
    float xs[4], cs[4];
#pragma unroll
    for (int si = 0; si < 4; si++) { xs[si] = x[gs + si]; cs[si] = g_c0[gs + si]; }
    float a[8][4], w1y[8], w4r[8];
#pragma unroll
    for (int r = 0; r < 8; r++) {
        int n = n0 + r;
        float w1x = W1[n * 3], w1c = W1[n * 3 + 2], bb = b1[n];
        w1y[r] = W1[n * 3 + 1]; w4r[r] = W4[n];
#pragma unroll
        for (int si = 0; si < 4; si++)
            a[r][si] = fmaf(w1x, xs[si], fmaf(w1c, cs[si], bb));
    }
    __syncthreads();

    float y[4] = {0.f, 0.f, 0.f, 0.f};
    for (int step = 0; step < nsteps; step++) {
        unsigned m1 = 0;
        float v[8][4];
#pragma unroll
        for (int r = 0; r < 8; r++)
#pragma unroll
            for (int si = 0; si < 4; si++) {
                float z = fmaf(w1y[r], y[si], a[r][si]);
                if (z > 0.f) m1 |= 1u << (r * 4 + si);
                v[r][si] = fmaxf(z, 0.f);
            }
        store_dup_d(ActA, n0, sG2, v);
        __syncthreads();

        u64 acc[16];
        {
            ulonglong2 ba = *(const ulonglong2*)(b2d + nG * 4);
            ulonglong2 bb = *(const ulonglong2*)(b2d + nG * 4 + 2);
#pragma unroll
            for (int si = 0; si < 4; si++) {
                acc[si] = ba.x; acc[4 + si] = ba.y;
                acc[8 + si] = bb.x; acc[12 + si] = bb.y;
            }
        }
        mv_d(W2T, ActA, n0, sG2, acc);
        unsigned m2 = 0;
        unpack_d(acc, v);
#pragma unroll
        for (int r = 0; r < 8; r++)
#pragma unroll
            for (int si = 0; si < 4; si++) {
                if (v[r][si] > 0.f) m2 |= 1u << (r * 4 + si);
                v[r][si] = fmaxf(v[r][si], 0.f);
            }
        store_dup_d(ActB, n0, sG2, v);
        __syncthreads();

        {
            ulonglong2 ba = *(const ulonglong2*)(b3d + nG * 4);
            ulonglong2 bb = *(const ulonglong2*)(b3d + nG * 4 + 2);
#pragma unroll
            for (int si = 0; si < 4; si++) {
                acc[si] = ba.x; acc[4 + si] = ba.y;
                acc[8 + si] = bb.x; acc[12 + si] = bb.y;
            }
        }
        mv_d(W3T, ActB, n0, sG2, acc);
        unpack_d(acc, v);
#pragma unroll
        for (int r = 0; r < 8; r++)
#pragma unroll
            for (int si = 0; si < 4; si++)
                v[r][si] = (v[r][si] > 0.f) ? w4r[r] : 0.f;
        store_dup_d(ActA, n0, sG2, v);
        __syncthreads();

#pragma unroll
        for (int q = 0; q < 16; q++) acc[q] = 0;
        mv_d(W3N, ActA, n0, sG2, acc);
        unpack_d(acc, v);
#pragma unroll
        for (int r = 0; r < 8; r++)
#pragma unroll
            for (int si = 0; si < 4; si++)
                v[r][si] = (m2 & (1u << (r * 4 + si))) ? v[r][si] : 0.f;
        store_dup_d(ActB, n0, sG2, v);
        __syncthreads();

#pragma unroll
        for (int q = 0; q < 16; q++) acc[q] = 0;
        mv_d(W2N, ActB, n0, sG2, acc);
        unpack_d(acc, v);
        float pg[4] = {0.f, 0.f, 0.f, 0.f};
#pragma unroll
        for (int r = 0; r < 8; r++)
#pragma unroll
            for (int si = 0; si < 4; si++) {
                float g = (m1 & (1u << (r * 4 + si))) ? v[r][si] : 0.f;
                pg[si] = fmaf(w1y[r], g, pg[si]);
            }
#pragma unroll
        for (int si = 0; si < 4; si++)
            pg[si] += __shfl_xor_sync(0xffffffffu, pg[si], 16);
        if (!(lane & 16))
            *(float4*)(red + warp * 64 + sG * 4) = make_float4(pg[0], pg[1], pg[2], pg[3]);
        __syncthreads();
        {
            float4 r0 = *(const float4*)(red + 0 * 64 + sG * 4);
            float4 r1 = *(const float4*)(red + 1 * 64 + sG * 4);
            float4 r2 = *(const float4*)(red + 2 * 64 + sG * 4);
            float4 r3 = *(const float4*)(red + 3 * 64 + sG * 4);
            y[0] -= LRATE * ((r0.x + r1.x) + (r2.x + r3.x));
            y[1] -= LRATE * ((r0.y + r1.y) + (r2.y + r3.y));
            y[2] -= LRATE * ((r0.z + r1.z) + (r2.z + r3.z));
            y[3] -= LRATE * ((r0.w + r1.w) + (r2.w + r3.w));
        }
    }
    if (nG == 0)
        *(float4*)(out + gs) = make_float4(y[0], y[1], y[2], y[3]);
}

// ---------------- Phase 2: mask-region cached stepping ----------------
__device__ __noinline__ float cold_build(
    const float* __restrict__ W2T, const float* __restrict__ W3T,
    const float* __restrict__ W2N, const float* __restrict__ W3N,
    const u64* __restrict__ b2p, const u64* __restrict__ b3p,
    float2* __restrict__ scf, u32* __restrict__ mkl,
    ulonglong2* __restrict__ rp2, ulonglong2* __restrict__ rp3,
    u64 apair, u64 w1yp, float w4lo, float w4hi, float y, int np)
{
    float* scu = (float*)scf;
    u64 ydup = pk2(y, y);
    u64 z1 = apair; fma2(z1, w1yp, ydup);
    float z1lo, z1hi; upk2(z1, z1lo, z1hi);
    bool m1lo = z1lo > 0.f, m1hi = z1hi > 0.f;
    float alo, ahi; upk2(apair, alo, ahi);
    float wylo, wyhi; upk2(w1yp, wylo, wyhi);
    scf[2 * np]     = make_float2(m1lo ? alo : 0.f, m1lo ? wylo : 0.f);
    scf[2 * np + 1] = make_float2(m1hi ? ahi : 0.f, m1hi ? wyhi : 0.f);
    __syncwarp();

    u64 Ra = b2p[np], Rb = 0, Pa = 0, Pb = 0;
#pragma unroll 4
    for (int k = 0; k < 32; k++) {
        float2 t0 = scf[k], t1 = scf[k + 32];
        u64 w0 = *(const u64*)(W2T + k * 64 + 2 * np);
        u64 w1 = *(const u64*)(W2T + (k + 32) * 64 + 2 * np);
        fma2(Ra, w0, pk2(t0.x, t0.x)); fma2(Pa, w0, pk2(t0.y, t0.y));
        fma2(Rb, w1, pk2(t1.x, t1.x)); fma2(Pb, w1, pk2(t1.y, t1.y));
    }
    u64 R2 = add2(Ra, Rb), P2 = add2(Pa, Pb);
    { ulonglong2 t; t.x = R2; t.y = P2; rp2[np] = t; }
    u64 z2 = R2; fma2(z2, P2, ydup);
    float z2lo, z2hi; upk2(z2, z2lo, z2hi);
    bool m2lo = z2lo > 0.f, m2hi = z2hi > 0.f;
    float rlo, rhi, plo, phi; upk2(R2, rlo, rhi); upk2(P2, plo, phi);
    __syncwarp();
    scf[2 * np]     = make_float2(m2lo ? rlo : 0.f, m2lo ? plo : 0.f);
    scf[2 * np + 1] = make_float2(m2hi ? rhi : 0.f, m2hi ? phi : 0.f);
    __syncwarp();

    Ra = b3p[np]; Rb = 0; Pa = 0; Pb = 0;
#pragma unroll 4
    for (int k = 0; k < 32; k++) {
        float2 t0 = scf[k], t1 = scf[k + 32];
        u64 w0 = *(const u64*)(W3T + k * 64 + 2 * np);
        u64 w1 = *(const u64*)(W3T + (k + 32) * 64 + 2 * np);
        fma2(Ra, w0, pk2(t0.x, t0.x)); fma2(Pa, w0, pk2(t0.y, t0.y));
        fma2(Rb, w1, pk2(t1.x, t1.x)); fma2(Pb, w1, pk2(t1.y, t1.y));
    }
    u64 R3 = add2(Ra, Rb), P3 = add2(Pa, Pb);
    { ulonglong2 t; t.x = R3; t.y = P3; rp3[np] = t; }
    u64 z3 = R3; fma2(z3, P3, ydup);
    float z3lo, z3hi; upk2(z3, z3lo, z3hi);
    bool m3lo = z3lo > 0.f, m3hi = z3hi > 0.f;

    mkl[np] = (m1lo ? 1u : 0u) | (m1hi ? 2u : 0u) | (m2lo ? 4u : 0u)
            | (m2hi ? 8u : 0u) | (m3lo ? 16u : 0u) | (m3hi ? 32u : 0u);

    __syncwarp();
    scu[2 * np]     = m3lo ? w4lo : 0.f;
    scu[2 * np + 1] = m3hi ? w4hi : 0.f;
    __syncwarp();
    u64 ta = 0, tb = 0;
#pragma unroll 4
    for (int j = 0; j < 32; j++) {
        float u0 = scu[j], u1 = scu[j + 32];
        fma2(ta, *(const u64*)(W3N + j * 64 + 2 * np), pk2(u0, u0));
        fma2(tb, *(const u64*)(W3N + (j + 32) * 64 + 2 * np), pk2(u1, u1));
    }
    u64 tt = add2(ta, tb);
    float tlo, thi; upk2(tt, tlo, thi);
    __syncwarp();
    scu[2 * np]     = m2lo ? tlo : 0.f;
    scu[2 * np + 1] = m2hi ? thi : 0.f;
    __syncwarp();
    ta = 0; tb = 0;
#pragma unroll 4
    for (int j = 0; j < 32; j++) {
        float v0 = scu[j], v1 = scu[j + 32];
        fma2(ta, *(const u64*)(W2N + j * 64 + 2 * np), pk2(v0, v0));
        fma2(tb, *(const u64*)(W2N + (j + 32) * 64 + 2 * np), pk2(v1, v1));
    }
    tt = add2(ta, tb);
    float wlo, whi; upk2(tt, wlo, whi);
    float pg = (m1lo ? wylo * wlo : 0.f) + (m1hi ? wyhi * whi : 0.f);
#pragma unroll
    for (int o = 1; o < 32; o <<= 1) pg += __shfl_xor_sync(0xffffffffu, pg, o);
    return pg;
}

__global__ __launch_bounds__(256, 1) void solver_cached(
    const float* __restrict__ x,
    const float* __restrict__ W1, const float* __restrict__ b1,
    const float* __restrict__ W2, const float* __restrict__ b2,
    const float* __restrict__ W3, const float* __restrict__ b3,
    const float* __restrict__ W4, float* __restrict__ out)
{
    extern __shared__ __align__(16) char sm[];
    float* W2T = (float*)sm;
    float* W3T = W2T + 4096;
    float* W2N = W3T + 4096;
    float* W3N = W2N + 4096;
    u64*   b2p = (u64*)(W3N + 4096);
    u64*   b3p = b2p + 32;
    ulonglong2* RP2 = (ulonglong2*)(b3p + 32);   // [128 entries][32 lanes]
    ulonglong2* RP3 = RP2 + 128 * 32;
    float2* SCF = (float2*)(RP3 + 128 * 32);     // [8 warps][64]
    u32*   MKL  = (u32*)(SCF + 8 * 64);          // [128 entries][32 lanes]

    int tid = threadIdx.x, np = tid & 31, w = tid >> 5;

    for (int i = tid; i < 1024; i += 256) {
        ((float4*)W2N)[i] = ((const float4*)W2)[i];
        ((float4*)W3N)[i] = ((const float4*)W3)[i];
    }
    __syncthreads();
    for (int i = tid; i < 4096; i += 256) {
        int n = i >> 6, k = i & 63;
        W2T[k * 64 + n] = W2N[i];
        W3T[k * 64 + n] = W3N[i];
    }
    if (tid < 32) {
        b2p[tid] = pk2(b2[2 * tid], b2[2 * tid + 1]);
        b3p[tid] = pk2(b3[2 * tid], b3[2 * tid + 1]);
    }
    __syncthreads();

    int gs = blockIdx.x * 64 + w * 8;
    float wy_lo = W1[(2 * np) * 3 + 1], wy_hi = W1[(2 * np + 1) * 3 + 1];
    u64 w1yp = pk2(wy_lo, wy_hi);
    float w4lo = W4[2 * np], w4hi = W4[2 * np + 1];
    float w1x0 = W1[(2 * np) * 3], w1c0 = W1[(2 * np) * 3 + 2], bb0 = b1[2 * np];
    float w1x1 = W1[(2 * np + 1) * 3], w1c1 = W1[(2 * np + 1) * 3 + 2], bb1 = b1[2 * np + 1];

    u64 ap[8]; float ys[8];
    u32 ypb[8];
#pragma unroll
    for (int s = 0; s < 8; s++) {
        float xv = x[gs + s], cv = g_c0[gs + s];
        ap[s] = pk2(fmaf(w1x0, xv, fmaf(w1c0, cv, bb0)),
                    fmaf(w1x1, xv, fmaf(w1c1, cv, bb1)));
        ys[s] = out[gs + s];
        ypb[s] = 0xFFFFFFFFu;          // never matches a real float's bits path
    }
    float2* scf = SCF + w * 64;
    float g0[8], g1[8];
    u32 validBits = 0, mruBits = 0, doneBits = 0;   // warp-uniform

    for (int t = 0; t < T_CACHED; t++) {
        if (doneBits == 0xFFu) break;
#pragma unroll
        for (int s = 0; s < 8; s++) {
            if ((doneBits >> s) & 1) continue;
            float y = ys[s];
            u64 ydup = pk2(y, y);
            u64 z1 = ap[s]; fma2(z1, w1yp, ydup);
            float z1lo, z1hi; upk2(z1, z1lo, z1hi);
            unsigned cur1 = (z1lo > 0.f ? 1u : 0u) | (z1hi > 0.f ? 2u : 0u);

            int e0 = (mruBits >> s) & 1;
            int hitE = -1;
#pragma unroll
            for (int tr = 0; tr < 2; tr++) {
                if (hitE >= 0) continue;
                int e = e0 ^ tr;
                if (!((validBits >> (e * 8 + s)) & 1)) continue;
                int base = (w * 2 + e) * 8 + s;
                u32 mb = MKL[base * 32 + np];
                ulonglong2 r2 = RP2[base * 32 + np];
                ulonglong2 r3 = RP3[base * 32 + np];
                u64 z2 = r2.x; fma2(z2, r2.y, ydup);
                u64 z3 = r3.x; fma2(z3, r3.y, ydup);
                float z2lo, z2hi, z3lo, z3hi;
                upk2(z2, z2lo, z2hi); upk2(z3, z3lo, z3hi);
                unsigned cur = cur1 | (z2lo > 0.f ? 4u : 0u) | (z2hi > 0.f ? 8u : 0u)
                             | (z3lo > 0.f ? 16u : 0u) | (z3hi > 0.f ? 32u : 0u);
                if (__ballot_sync(0xffffffffu, cur == mb) == 0xffffffffu) hitE = e;
            }

            float ynew;
            if (hitE >= 0) {
                ynew = y - LRATE * (hitE ? g1[s] : g0[s]);
                mruBits = (mruBits & ~(1u << s)) | ((u32)hitE << s);
            } else {
                int e = e0 ^ 1;
                int base = (w * 2 + e) * 8 + s;
                float gy = cold_build(W2T, W3T, W2N, W3N, b2p, b3p, scf,
                                      MKL + base * 32, RP2 + base * 32,
                                      RP3 + base * 32,
                                      ap[s], w1yp, w4lo, w4hi, y, np);
                if (e) g1[s] = gy; else g0[s] = gy;
                validBits |= 1u << (e * 8 + s);
                mruBits = (mruBits & ~(1u << s)) | ((u32)e << s);
                ynew = y - LRATE * gy;
            }

            // ---- exact-cycle detection (bitwise; map f(y) is pure) ----
            u32 nb = __float_as_uint(ynew), cb = __float_as_uint(y);
            if (nb == cb) {                       // period-1 fixed point
                ys[s] = ynew; doneBits |= 1u << s;
            } else if (nb == ypb[s]) {            // period-2 cycle
                int R = T_CACHED - 1 - t;         // steps remaining after this one
                ys[s] = (R & 1) ? y : ynew;
                doneBits |= 1u << s;
            } else {
                ypb[s] = cb;
                ys[s] = ynew;
            }
        }
    }

    if (np == 0) {
#pragma unroll
        for (int s = 0; s < 8; s++) out[gs + s] = ys[s];
    }
}

// ---------------- Launch ----------------
extern "C" void kernel_launch(void* const* d_in, const int* in_sizes, int n_in,
                              void* d_out, int out_size) {
    const float* x  = (const float*)d_in[0];
    const float* c  = (const float*)d_in[1];
    const float* W1 = (const float*)d_in[2];
    const float* b1 = (const float*)d_in[3];
    const float* W2 = (const float*)d_in[4];
    const float* b2 = (const float*)d_in[5];
    const float* W3 = (const float*)d_in[6];
    const float* b3 = (const float*)d_in[7];
    const float* W4 = (const float*)d_in[8];
    float* out = (float*)d_out;
    int B = in_sizes[0];

    const int SMEM_D = 4 * 4096 * 4 + 2 * 4096 * 8 + 64 * 8 + 256 * 4;   // 132608
    const int SMEM_C = 4 * 4096 * 4 + 64 * 8 + 2 * 128 * 32 * 16
                     + 8 * 64 * 8 + 128 * 32 * 4;                        // 217600
    cudaFuncSetAttribute(solver_dense,
                         cudaFuncAttributeMaxDynamicSharedMemorySize, SMEM_D);
    cudaFuncSetAttribute(solver_cached,
                         cudaFuncAttributeMaxDynamicSharedMemorySize, SMEM_C);

    nn_kernel<<<(B + 7) / 8, 256>>>(c, B);
    solver_dense<<<B / 64, 128, SMEM_D>>>(x, W1, b1, W2, b2, W3, b3, W4, out, T_DENSE);
    solver_cached<<<B / 64, 256, SMEM_C>>>(x, W1, b1, W2, b2, W3, b3, W4, out);
}

// round 17
// speedup vs baseline: 1.0020x; 1.0020x over previous
#include <cuda_runtime.h>

#define NSTEPS 50
#define LRATE  0.1f
#define BMAX   8192

__device__ float g_c0[BMAX];
typedef unsigned long long u64;
typedef unsigned int u32;

__device__ __forceinline__ u64 pk2(float lo, float hi) {
    u64 r; asm("mov.b64 %0, {%1,%2};" : "=l"(r) : "f"(lo), "f"(hi)); return r;
}
__device__ __forceinline__ void upk2(u64 v, float& lo, float& hi) {
    asm("mov.b64 {%0,%1}, %2;" : "=f"(lo), "=f"(hi) : "l"(v));
}
__device__ __forceinline__ void fma2(u64& d, u64 a, u64 b) {
    asm("fma.rn.f32x2 %0, %1, %2, %0;" : "+l"(d) : "l"(a), "l"(b));
}

// ---------------- Kernel 1: 1-D nearest neighbor ----------------
// |ci-cj| == sqrt((ci-cj)^2) exactly in RN fp32.
#define NN_TILE 2048
__global__ __launch_bounds__(256) void nn_kernel(const float* __restrict__ c, int B) {
    __shared__ float ct[NN_TILE];
    int lane = threadIdx.x & 31, w = threadIdx.x >> 5, q = blockIdx.x * 8 + w;
    float cq = (q < B) ? c[q] : 0.f;
    float bestD = 3.0e38f; int bestJ = 0;
    for (int t0 = 0; t0 < B; t0 += NN_TILE) {
        int nt = min(NN_TILE, B - t0);
        __syncthreads();
        for (int i = threadIdx.x; i < nt; i += 256) ct[i] = c[t0 + i];
        __syncthreads();
        for (int jj = lane; jj < nt; jj += 32) {
            int j = t0 + jj;
            float d = fabsf(cq - ct[jj]);
            if (j == q) d += 1e9f;
            if (d < bestD) { bestD = d; bestJ = j; }
        }
    }
#pragma unroll
    for (int off = 16; off; off >>= 1) {
        float dO = __shfl_down_sync(0xffffffffu, bestD, off);
        int   jO = __shfl_down_sync(0xffffffffu, bestJ, off);
        if (dO < bestD || (dO == bestD && jO < bestJ)) { bestD = dO; bestJ = jO; }
    }
    if (lane == 0 && q < B) g_c0[q] = c[bestJ];
}

// ---------------- Unified solver: hits + batched cold waves ----------------
// Warp owns 8 samples; lane np owns neuron pair (2np, 2np+1).
// Cache: 2 entries/sample of {packed 6-bit masks/lane, R2/P2, R3/P3, gy}.
// A step: z1 from registers; verify entry (affine z2/z3 + one ballot); on hit
// y -= 0.1*gy. Misses rebuilt in 2 waves of <=4 samples sharing weight loads.
__global__ __launch_bounds__(256, 1) void solver_unified(
    const float* __restrict__ x,
    const float* __restrict__ W1, const float* __restrict__ b1,
    const float* __restrict__ W2, const float* __restrict__ b2,
    const float* __restrict__ W3, const float* __restrict__ b3,
    const float* __restrict__ W4, float* __restrict__ out)
{
    extern __shared__ __align__(16) char sm[];
    float* W2T = (float*)sm;                      // [64][64] W2T[k][n]=W2[n][k]
    float* W3T = W2T + 4096;
    float* W2N = W3T + 4096;                      // natural
    float* W3N = W2N + 4096;
    u64*   b2p = (u64*)(W3N + 4096);              // [32]
    u64*   b3p = b2p + 32;
    ulonglong2* RP2 = (ulonglong2*)(b3p + 32);    // [128 entries][32]
    ulonglong2* RP3 = RP2 + 128 * 32;
    u32*   MKLp = (u32*)(RP3 + 128 * 32);         // [64 samples][32]: 2x6 bits
    float2* SCF = (float2*)(MKLp + 64 * 32);      // [8 warps][4 slots][64]

    int tid = threadIdx.x, np = tid & 31, w = tid >> 5;

    for (int i = tid; i < 1024; i += 256) {
        ((float4*)W2N)[i] = ((const float4*)W2)[i];
        ((float4*)W3N)[i] = ((const float4*)W3)[i];
    }
    __syncthreads();
    for (int i = tid; i < 4096; i += 256) {
        int n = i >> 6, k = i & 63;
        W2T[k * 64 + n] = W2N[i];
        W3T[k * 64 + n] = W3N[i];
    }
    if (tid < 32) {
        b2p[tid] = pk2(b2[2 * tid], b2[2 * tid + 1]);
        b3p[tid] = pk2(b3[2 * tid], b3[2 * tid + 1]);
    }
    __syncthreads();

    int gs = blockIdx.x * 64 + w * 8;
    float wylo = W1[(2 * np) * 3 + 1], wyhi = W1[(2 * np + 1) * 3 + 1];
    u64 w1yp = pk2(wylo, wyhi);
    float w4lo = W4[2 * np], w4hi = W4[2 * np + 1];
    float w1x0 = W1[(2 * np) * 3], w1c0 = W1[(2 * np) * 3 + 2], bb0 = b1[2 * np];
    float w1x1 = W1[(2 * np + 1) * 3], w1c1 = W1[(2 * np + 1) * 3 + 2], bb1 = b1[2 * np + 1];

    u64 ap[8]; float ys[8], g0[8], g1[8];
#pragma unroll
    for (int s = 0; s < 8; s++) {
        float xv = x[gs + s], cv = g_c0[gs + s];
        ap[s] = pk2(fmaf(w1x0, xv, fmaf(w1c0, cv, bb0)),
                    fmaf(w1x1, xv, fmaf(w1c1, cv, bb1)));
        ys[s] = 0.f;                       // Y_MEAN = 0
    }
    float2* scfw = SCF + w * 256;          // this warp's 4x64 float2 scratch
    float*  scu  = (float*)scfw;           // per-slot q: floats [q*128 .. q*128+63]
    u32 validBits = 0, mruBits = 0;        // warp-uniform

#pragma unroll 1
    for (int t = 0; t < NSTEPS; t++) {
        u32 missBits = 0;
#pragma unroll
        for (int s = 0; s < 8; s++) {
            float y = ys[s]; u64 ydup = pk2(y, y);
            u64 z1 = ap[s]; fma2(z1, w1yp, ydup);
            float z1lo, z1hi; upk2(z1, z1lo, z1hi);
            unsigned cur1 = (z1lo > 0.f ? 1u : 0u) | (z1hi > 0.f ? 2u : 0u);
            int e0 = (mruBits >> s) & 1, hitE = -1;
#pragma unroll
            for (int tr = 0; tr < 2; tr++) {
                if (hitE >= 0) continue;
                int e = e0 ^ tr;
                if (!((validBits >> (e * 8 + s)) & 1)) continue;
                int base = (w * 2 + e) * 8 + s;
                u32 mb = (MKLp[(w * 8 + s) * 32 + np] >> (6 * e)) & 0x3Fu;
                ulonglong2 r2 = RP2[base * 32 + np], r3 = RP3[base * 32 + np];
                u64 z2 = r2.x; fma2(z2, r2.y, ydup);
                u64 z3 = r3.x; fma2(z3, r3.y, ydup);
                float a2, c2, a3, c3; upk2(z2, a2, c2); upk2(z3, a3, c3);
                unsigned cur = cur1 | (a2 > 0.f ? 4u : 0u) | (c2 > 0.f ? 8u : 0u)
                             | (a3 > 0.f ? 16u : 0u) | (c3 > 0.f ? 32u : 0u);
                if (__ballot_sync(0xffffffffu, cur == mb) == 0xffffffffu) hitE = e;
            }
            if (hitE >= 0) {
                ys[s] = y - LRATE * (hitE ? g1[s] : g0[s]);
                mruBits = (mruBits & ~(1u << s)) | ((u32)hitE << s);
            } else missBits |= 1u << s;
        }

        if (missBits) {
#pragma unroll
            for (int wave = 0; wave < 2; wave++) {
                u32 wm = (missBits >> (wave * 4)) & 0xFu;
                if (!wm) continue;
                bool m1L[4] = {0,0,0,0}, m1H[4] = {0,0,0,0};
                bool m2L[4] = {0,0,0,0}, m2H[4] = {0,0,0,0};
                // Phase A: masked (a, w1y) per miss slot
#pragma unroll
                for (int q = 0; q < 4; q++) if ((wm >> q) & 1) {
                    int s = wave * 4 + q;
                    float y = ys[s]; u64 yd = pk2(y, y);
                    u64 z1 = ap[s]; fma2(z1, w1yp, yd);
                    float zlo, zhi; upk2(z1, zlo, zhi);
                    m1L[q] = zlo > 0.f; m1H[q] = zhi > 0.f;
                    float alo, ahi; upk2(ap[s], alo, ahi);
                    scfw[q * 64 + 2 * np]     = make_float2(m1L[q] ? alo : 0.f, m1L[q] ? wylo : 0.f);
                    scfw[q * 64 + 2 * np + 1] = make_float2(m1H[q] ? ahi : 0.f, m1H[q] ? wyhi : 0.f);
                }
                __syncwarp();
                // Phase B: fwd2 batched matvec (weights shared across slots)
                u64 R[4], P[4];
#pragma unroll
                for (int q = 0; q < 4; q++) { R[q] = b2p[np]; P[q] = 0; }
#pragma unroll 8
                for (int k = 0; k < 64; k++) {
                    u64 wp = *(const u64*)(W2T + k * 64 + 2 * np);
                    float2 t0 = scfw[k], t1 = scfw[64 + k],
                           t2 = scfw[128 + k], t3 = scfw[192 + k];
                    fma2(R[0], wp, pk2(t0.x, t0.x)); fma2(P[0], wp, pk2(t0.y, t0.y));
                    fma2(R[1], wp, pk2(t1.x, t1.x)); fma2(P[1], wp, pk2(t1.y, t1.y));
                    fma2(R[2], wp, pk2(t2.x, t2.x)); fma2(P[2], wp, pk2(t2.y, t2.y));
                    fma2(R[3], wp, pk2(t3.x, t3.x)); fma2(P[3], wp, pk2(t3.y, t3.y));
                }
                __syncwarp();
#pragma unroll
                for (int q = 0; q < 4; q++) if ((wm >> q) & 1) {
                    int s = wave * 4 + q, e = ((mruBits >> s) & 1) ^ 1;
                    int base = (w * 2 + e) * 8 + s;
                    float y = ys[s]; u64 yd = pk2(y, y);
                    u64 z2 = R[q]; fma2(z2, P[q], yd);
                    float zlo, zhi; upk2(z2, zlo, zhi);
                    m2L[q] = zlo > 0.f; m2H[q] = zhi > 0.f;
                    ulonglong2 st; st.x = R[q]; st.y = P[q];
                    RP2[base * 32 + np] = st;
                    float rlo, rhi, plo, phi; upk2(R[q], rlo, rhi); upk2(P[q], plo, phi);
                    scfw[q * 64 + 2 * np]     = make_float2(m2L[q] ? rlo : 0.f, m2L[q] ? plo : 0.f);
                    scfw[q * 64 + 2 * np + 1] = make_float2(m2H[q] ? rhi : 0.f, m2H[q] ? phi : 0.f);
                }
                __syncwarp();
                // Phase C: fwd3 batched matvec
#pragma unroll
                for (int q = 0; q < 4; q++) { R[q] = b3p[np]; P[q] = 0; }
#pragma unroll 8
                for (int k = 0; k < 64; k++) {
                    u64 wp = *(const u64*)(W3T + k * 64 + 2 * np);
                    float2 t0 = scfw[k], t1 = scfw[64 + k],
                           t2 = scfw[128 + k], t3 = scfw[192 + k];
                    fma2(R[0], wp, pk2(t0.x, t0.x)); fma2(P[0], wp, pk2(t0.y, t0.y));
                    fma2(R[1], wp, pk2(t1.x, t1.x)); fma2(P[1], wp, pk2(t1.y, t1.y));
                    fma2(R[2], wp, pk2(t2.x, t2.x)); fma2(P[2], wp, pk2(t2.y, t2.y));
                    fma2(R[3], wp, pk2(t3.x, t3.x)); fma2(P[3], wp, pk2(t3.y, t3.y));
                }
                __syncwarp();
#pragma unroll
                for (int q = 0; q < 4; q++) if ((wm >> q) & 1) {
                    int s = wave * 4 + q, e = ((mruBits >> s) & 1) ^ 1;
                    int base = (w * 2 + e) * 8 + s;
                    float y = ys[s]; u64 yd = pk2(y, y);
                    u64 z3 = R[q]; fma2(z3, P[q], yd);
                    float zlo, zhi; upk2(z3, zlo, zhi);
                    bool m3L = zlo > 0.f, m3H = zhi > 0.f;
                    ulonglong2 st; st.x = R[q]; st.y = P[q];
                    RP3[base * 32 + np] = st;
                    u32 bits = (m1L[q] ? 1u : 0u) | (m1H[q] ? 2u : 0u)
                             | (m2L[q] ? 4u : 0u) | (m2H[q] ? 8u : 0u)
                             | (m3L ? 16u : 0u) | (m3H ? 32u : 0u);
                    u32 idx = (w * 8 + s) * 32 + np;
                    u32 old = MKLp[idx];
                    MKLp[idx] = (old & ~(0x3Fu << (6 * e))) | (bits << (6 * e));
                    scu[q * 128 + 2 * np]     = m3L ? w4lo : 0.f;
                    scu[q * 128 + 2 * np + 1] = m3H ? w4hi : 0.f;
                }
                __syncwarp();
                // Phase D: bwd3 batched (t = W3^T u)
                u64 T[4] = {0, 0, 0, 0};
#pragma unroll 8
                for (int j = 0; j < 64; j++) {
                    u64 wp = *(const u64*)(W3N + j * 64 + 2 * np);
                    float u0 = scu[j], u1 = scu[128 + j],
                          u2 = scu[256 + j], u3 = scu[384 + j];
                    fma2(T[0], wp, pk2(u0, u0)); fma2(T[1], wp, pk2(u1, u1));
                    fma2(T[2], wp, pk2(u2, u2)); fma2(T[3], wp, pk2(u3, u3));
                }
                __syncwarp();
#pragma unroll
                for (int q = 0; q < 4; q++) if ((wm >> q) & 1) {
                    float tlo, thi; upk2(T[q], tlo, thi);
                    scu[q * 128 + 2 * np]     = m2L[q] ? tlo : 0.f;
                    scu[q * 128 + 2 * np + 1] = m2H[q] ? thi : 0.f;
                }
                __syncwarp();
                // Phase E: bwd2 batched (v = W2^T g2) -> gy
#pragma unroll
                for (int q = 0; q < 4; q++) T[q] = 0;
#pragma unroll 8
                for (int j = 0; j < 64; j++) {
                    u64 wp = *(const u64*)(W2N + j * 64 + 2 * np);
                    float u0 = scu[j], u1 = scu[128 + j],
                          u2 = scu[256 + j], u3 = scu[384 + j];
                    fma2(T[0], wp, pk2(u0, u0)); fma2(T[1], wp, pk2(u1, u1));
                    fma2(T[2], wp, pk2(u2, u2)); fma2(T[3], wp, pk2(u3, u3));
                }
                float pg[4];
#pragma unroll
                for (int q = 0; q < 4; q++) {
                    float wlo, whi; upk2(T[q], wlo, whi);
                    pg[q] = (m1L[q] ? wylo * wlo : 0.f) + (m1H[q] ? wyhi * whi : 0.f);
#pragma unroll
                    for (int o = 1; o < 32; o <<= 1)
                        pg[q] += __shfl_xor_sync(0xffffffffu, pg[q], o);
                }
#pragma unroll
                for (int q = 0; q < 4; q++) if ((wm >> q) & 1) {
                    int s = wave * 4 + q, e = ((mruBits >> s) & 1) ^ 1;
                    if (e) g1[s] = pg[q]; else g0[s] = pg[q];
                    validBits |= 1u << (e * 8 + s);
                    mruBits = (mruBits & ~(1u << s)) | ((u32)e << s);
                    ys[s] -= LRATE * pg[q];
                }
                __syncwarp();
            }
        }
    }

    if (np == 0) {
#pragma unroll
        for (int s = 0; s < 8; s++) out[gs + s] = ys[s];
    }
}

// ---------------- Launch ----------------
extern "C" void kernel_launch(void* const* d_in, const int* in_sizes, int n_in,
                              void* d_out, int out_size) {
    const float* x  = (const float*)d_in[0];
    const float* c  = (const float*)d_in[1];
    const float* W1 = (const float*)d_in[2];
    const float* b1 = (const float*)d_in[3];
    const float* W2 = (const float*)d_in[4];
    const float* b2 = (const float*)d_in[5];
    const float* W3 = (const float*)d_in[6];
    const float* b3 = (const float*)d_in[7];
    const float* W4 = (const float*)d_in[8];
    // d_in[9] = b4: constant offset, no effect on dE/dy
    float* out = (float*)d_out;
    int B = in_sizes[0];

    // 65536 (weights) + 512 (bias) + 131072 (RP2+RP3) + 8192 (MKLp) + 16384 (SCF)
    const int SMEM = 4 * 4096 * 4 + 64 * 8 + 2 * 128 * 32 * 16
                   + 64 * 32 * 4 + 8 * 256 * 8;   // 221696 B
    cudaFuncSetAttribute(solver_unified,
                         cudaFuncAttributeMaxDynamicSharedMemorySize, SMEM);

    nn_kernel<<<(B + 7) / 8, 256>>>(c, B);
    solver_unified<<<B / 64, 256, SMEM>>>(x, W1, b1, W2, b2, W3, b3, W4, out);
}